// round 13
// baseline (speedup 1.0000x reference)
#include <cuda_runtime.h>

#define NQ1 10001
#define NC1 301
#define ND1 200
#define NA1 20002

// ---- device scratch (static globals: no runtime allocation) ----
__device__ float g_C23 [128*256];   // [W2|W3] row-major (GEMM B operand)
__device__ float g_W45a[128*256];   // [W4[128:],W5[128:]]
__device__ float g_b45 [256];
__device__ float g_b23 [256];       // [b2|b3]
__device__ float g_cst23[256];      // b1@C23 + [b2|b3]
__device__ float g_G   [512*256];   // W1 @ C23
__device__ float g_TQ  [NQ1*256];
__device__ float g_TC  [NC1*256];
__device__ float g_TS1 [ND1*256];
__device__ float g_TD1 [ND1*256];
__device__ float g_TA45[NA1*256];
__device__ float g_TA6 [NA1*128];
__device__ float g_TS6 [ND1*128];
__device__ float g_TD6 [ND1*128];

__device__ __forceinline__ float sigm(float x) { return 1.f / (1.f + __expf(-x)); }
__device__ __forceinline__ float tanh_fast(float x) {
    float y; asm("tanh.approx.f32 %0, %1;" : "=f"(y) : "f"(x)); return y;
}

// ---------------------------------------------------------------------------
__global__ void prep_concat(const float* __restrict__ W2, const float* __restrict__ W3,
                            const float* __restrict__ W4, const float* __restrict__ W5,
                            const float* __restrict__ b2, const float* __restrict__ b3,
                            const float* __restrict__ b4, const float* __restrict__ b5)
{
    int e = blockIdx.x * 256 + threadIdx.x;
    if (e < 128*256) {
        int i = e >> 8, j = e & 255;
        g_C23 [e] = (j < 128) ? W2[i*128 + j]       : W3[i*128 + (j-128)];
        g_W45a[e] = (j < 128) ? W4[(128+i)*128 + j] : W5[(128+i)*128 + (j-128)];
    }
    if (e < 256) {
        g_b45[e] = (e < 128) ? b4[e] : b5[e-128];
        g_b23[e] = (e < 128) ? b2[e] : b3[e-128];
    }
}

// ---------------------------------------------------------------------------
// batched table GEMM: C[M,N] = A[M,128]@B[128,N] (+bias)
// 256 thr, 64 rows/block, 8 rows/warp.
// ---------------------------------------------------------------------------
struct GDesc { const float *A, *B, *bias; float *C; int M, N; };
struct GBatch { GDesc g[6]; int start[7]; int n; };

__global__ void gemm_batched(GBatch bt)
{
    __shared__ float As[64*128];
    int gi = 0;
    while (gi < bt.n - 1 && (int)blockIdx.x >= bt.start[gi+1]) gi++;
    const GDesc d = bt.g[gi];
    const int blk = blockIdx.x - bt.start[gi];

    const int tid = threadIdx.x, w = tid >> 5, lane = tid & 31;
    const int row0 = blk * 64;
    for (int e = tid; e < 8192; e += 256) {
        int rr = e >> 7, ii = e & 127, gr = row0 + rr;
        As[e] = (gr < d.M) ? d.A[gr*128 + ii] : 0.f;
    }
    __syncthreads();
    const int r0 = w * 8;
    for (int jo = 0; jo < d.N; jo += 128) {
        const int j = jo + lane * 4;
        float acc[8][4] = {};
        const float* Bp = d.B + j;
        #pragma unroll 2
        for (int i = 0; i < 128; i++) {
            float4 bb = *reinterpret_cast<const float4*>(Bp + i*d.N);
            #pragma unroll
            for (int rr = 0; rr < 8; rr++) {
                float av = As[(r0 + rr)*128 + i];
                acc[rr][0] += av*bb.x; acc[rr][1] += av*bb.y;
                acc[rr][2] += av*bb.z; acc[rr][3] += av*bb.w;
            }
        }
        float4 bv = d.bias ? *reinterpret_cast<const float4*>(d.bias + j)
                           : make_float4(0.f, 0.f, 0.f, 0.f);
        #pragma unroll
        for (int rr = 0; rr < 8; rr++) {
            int row = row0 + r0 + rr;
            if (row < d.M) {
                float4 o;
                o.x = acc[rr][0]+bv.x; o.y = acc[rr][1]+bv.y;
                o.z = acc[rr][2]+bv.z; o.w = acc[rr][3]+bv.w;
                *reinterpret_cast<float4*>(d.C + row*d.N + j) = o;
            }
        }
    }
}

// ---------------------------------------------------------------------------
// scan: 64 CTAs, 256 threads, G=2 batch rows per CTA.
// Weights (C23t transposed stride-132, W6t, w45-in-regs) loaded ONCE per step,
// used for BOTH rows. Row 0 handled by t<128 in scalar stages, row 1 by t>=128.
// ---------------------------------------------------------------------------
#define C23T_STRIDE 132
#define OFF_C23  0
#define OFF_W6   (OFF_C23 + 256*132)        // 33792
#define OFF_WF   (OFF_W6  + 128*132)        // +16896
#define OFF_KV0  (OFF_WF  + 1280)
#define OFF_KV1  (OFF_KV0 + 128)
#define OFF_SD0  (OFF_KV1 + 128)
#define OFF_SD1  (OFF_SD0 + 128)
#define OFF_ZB0  (OFF_SD1 + 128)
#define OFF_ZB1  (OFF_ZB0 + 256)
#define OFF_G60  (OFF_ZB1 + 256)
#define OFF_G61  (OFF_G60 + 256)
#define OFF_PB0  (OFF_G61 + 256)
#define OFF_PB1  (OFF_PB0 + 256)
#define OFF_LP0  (OFF_PB1 + 256)
#define OFF_LP1  (OFF_LP0 + 80)
#define SCAN_SMEM_FLOATS (OFF_LP1 + 80)
#define SCAN_SMEM_BYTES  (SCAN_SMEM_FLOATS * 4)

__global__ void __launch_bounds__(256, 1)
scan_kernel(const int* __restrict__ qi_, const int* __restrict__ ci_,
            const int* __restrict__ si_, const int* __restrict__ di_,
            const int* __restrict__ ai_,
            const float* __restrict__ knowledge,
            const float* __restrict__ W2, const float* __restrict__ W3,
            const float* __restrict__ W4, const float* __restrict__ W5,
            const float* __restrict__ W6,
            const float* __restrict__ Wf, const float* __restrict__ bf,
            float* __restrict__ out)
{
    extern __shared__ float sm[];
    float* kv0 = sm + OFF_KV0;  float* kv1 = sm + OFF_KV1;
    float* sd0 = sm + OFF_SD0;  float* sd1 = sm + OFF_SD1;
    float* zb0 = sm + OFF_ZB0;  float* zb1 = sm + OFF_ZB1;
    float* g60 = sm + OFF_G60;  float* g61 = sm + OFF_G61;
    float* pb0 = sm + OFF_PB0;  float* pb1 = sm + OFF_PB1;
    float* lp0 = sm + OFF_LP0;  float* lp1 = sm + OFF_LP1;

    const int b = blockIdx.x, t = threadIdx.x;

    // transposed weight fills
    for (int e = t; e < 128*256; e += 256) {
        int i = e >> 8, j = e & 255;
        float v = (j < 128) ? W2[i*128 + j] : W3[i*128 + (j-128)];
        sm[OFF_C23 + j*C23T_STRIDE + i] = v;
    }
    for (int e = t; e < 128*128; e += 256) {
        int i = e >> 7, c = e & 127;
        sm[OFF_W6 + c*C23T_STRIDE + i] = W6[i*128 + c];
    }
    for (int e = t; e < 1280; e += 256) {
        int o = e >> 7, i = e & 127;
        sm[OFF_WF + o*128 + i] = Wf[i*10 + o];
    }
    if (t < 128) { kv0[t] = knowledge[t]; kv1[t] = knowledge[t]; }

    // register-resident [W4|W5] column t (fully unrolled -> true registers)
    float w45[128];
    {
        const float* Ws = (t < 128) ? W4 : W5;
        const int col = t & 127;
        #pragma unroll
        for (int i = 0; i < 128; i++) w45[i] = Ws[i*128 + col];
    }
    const float bfreg = ((t & 127) < 10) ? bf[t & 127] : 0.f;
    __syncthreads();

    const bool low = (t < 128);
    const int cl = t & 127;                 // half-column id
    const int half0 = (t >> 7) * 64;        // split-K half for g6 partial
    const int r0 = 2*b, r1 = 2*b + 1;
    const int gb0 = r0 * 512, gb1 = r1 * 512;
    float* outp0 = out + r0 * 5120;
    float* outp1 = out + r1 * 5120;

    // prefetch step-0 streams (both rows, column t)
    float xqa, xca, xsa, xda, a45a;         // row0 streams
    float xqb, xcb, xsb, xdb, a45b;         // row1 streams
    float r6a = 0.f, r6s = 0.f, r6d = 0.f;  // own-row gate streams (col cl)
    {
        int qA = qi_[gb0], cA = ci_[gb0], sA = si_[gb0], dA = di_[gb0], aA = ai_[gb0];
        int qB = qi_[gb1], cB = ci_[gb1], sB = si_[gb1], dB = di_[gb1], aB = ai_[gb1];
        xqa = g_TQ[qA*256 + t];  xca = g_TC[cA*256 + t];
        xsa = g_TS1[sA*256 + t]; xda = g_TD1[dA*256 + t];
        a45a = g_TA45[aA*256 + t];
        xqb = g_TQ[qB*256 + t];  xcb = g_TC[cB*256 + t];
        xsb = g_TS1[sB*256 + t]; xdb = g_TD1[dB*256 + t];
        a45b = g_TA45[aB*256 + t];
        int ag = low ? aA : aB, sg = low ? sA : sB, dg = low ? dA : dB;
        r6a = g_TA6[ag*128 + cl]; r6s = g_TS6[sg*128 + cl]; r6d = g_TD6[dg*128 + cl];
    }

    const float* wc  = sm + OFF_C23 + t*C23T_STRIDE;
    const float* w6p = sm + OFF_W6 + cl*C23T_STRIDE + half0;

    for (int stp = 0; stp < 512; stp++) {
        const float x23a = (xqa + xca) + (xsa + xda);
        const float x23b = (xqb + xcb) + (xsb + xdb);
        const float a45ca = a45a, a45cb = a45b;
        const float r6c  = (r6a + r6s) + r6d;

        if (stp + 1 < 512) {
            int gA = gb0 + stp + 1, gB = gb1 + stp + 1;
            int qA = qi_[gA], cA = ci_[gA], sA = si_[gA], dA = di_[gA], aA = ai_[gA];
            int qB = qi_[gB], cB = ci_[gB], sB = si_[gB], dB = di_[gB], aB = ai_[gB];
            xqa = g_TQ[qA*256 + t];  xca = g_TC[cA*256 + t];
            xsa = g_TS1[sA*256 + t]; xda = g_TD1[dA*256 + t];
            a45a = g_TA45[aA*256 + t];
            xqb = g_TQ[qB*256 + t];  xcb = g_TC[cB*256 + t];
            xsb = g_TS1[sB*256 + t]; xdb = g_TD1[dB*256 + t];
            a45b = g_TA45[aB*256 + t];
            int ag = low ? aA : aB, sg = low ? sA : sB, dg = low ? dA : dB;
            r6a = g_TA6[ag*128 + cl]; r6s = g_TS6[sg*128 + cl]; r6d = g_TD6[dg*128 + cl];
        }

        // ---- S1: z(col t) for both rows; g6 half-partials for both rows ----
        float A0=0.f,A1=0.f,A2=0.f,A3=0.f;      // row0
        float B0=0.f,B1=0.f,B2=0.f,B3=0.f;      // row1
        #pragma unroll
        for (int i = 0; i < 128; i += 4) {
            float4 w4 = *reinterpret_cast<const float4*>(wc + i);
            float4 ka = *reinterpret_cast<const float4*>(kv0 + i);
            float4 kb = *reinterpret_cast<const float4*>(kv1 + i);
            A0 += ka.x * w4.x; A1 += ka.y * w4.y;
            A2 += ka.z * w4.z; A3 += ka.w * w4.w;
            B0 += kb.x * w4.x; B1 += kb.y * w4.y;
            B2 += kb.z * w4.z; B3 += kb.w * w4.w;
        }
        float Ga0=0.f,Ga1=0.f,Ga2=0.f,Ga3=0.f;
        float Gb0=0.f,Gb1=0.f,Gb2=0.f,Gb3=0.f;
        #pragma unroll
        for (int i = 0; i < 64; i += 4) {
            float4 w4 = *reinterpret_cast<const float4*>(w6p + i);
            float4 ka = *reinterpret_cast<const float4*>(kv0 + half0 + i);
            float4 kb = *reinterpret_cast<const float4*>(kv1 + half0 + i);
            Ga0 += ka.x * w4.x; Ga1 += ka.y * w4.y;
            Ga2 += ka.z * w4.z; Ga3 += ka.w * w4.w;
            Gb0 += kb.x * w4.x; Gb1 += kb.y * w4.y;
            Gb2 += kb.z * w4.z; Gb3 += kb.w * w4.w;
        }
        zb0[t] = x23a - ((A0+A1)+(A2+A3));
        zb1[t] = x23b - ((B0+B1)+(B2+B3));
        g60[t] = (Ga0+Ga1)+(Ga2+Ga3);
        g61[t] = (Gb0+Gb1)+(Gb2+Gb3);
        __syncthreads();   // B1

        // ---- S2: sdf + gate; t<128 -> row0, t>=128 -> row1 ----
        float greg, kold;
        if (low) {
            sd0[cl] = sigm(zb0[cl]) * tanh_fast(zb0[128 + cl]);
            greg = sigm(g60[cl] + g60[128 + cl] + r6c);
            kold = kv0[cl];
        } else {
            sd1[cl] = sigm(zb1[cl]) * tanh_fast(zb1[128 + cl]);
            greg = sigm(g61[cl] + g61[128 + cl] + r6c);
            kold = kv1[cl];
        }
        __syncthreads();   // B2

        // ---- S3: P(col t) for both rows (w45 in regs, sdf broadcast LDS) ----
        float P0=0.f,P1=0.f,P2=0.f,P3=0.f;
        float Q0=0.f,Q1=0.f,Q2=0.f,Q3=0.f;
        #pragma unroll
        for (int i = 0; i < 128; i += 4) {
            float4 sa = *reinterpret_cast<const float4*>(sd0 + i);
            float4 sb = *reinterpret_cast<const float4*>(sd1 + i);
            P0 += sa.x * w45[i+0]; P1 += sa.y * w45[i+1];
            P2 += sa.z * w45[i+2]; P3 += sa.w * w45[i+3];
            Q0 += sb.x * w45[i+0]; Q1 += sb.y * w45[i+1];
            Q2 += sb.z * w45[i+2]; Q3 += sb.w * w45[i+3];
        }
        pb0[t] = ((P0+P1)+(P2+P3)) + a45ca;
        pb1[t] = ((Q0+Q1)+(Q2+Q3)) + a45cb;
        __syncthreads();   // B3

        // ---- S4: k update; t<128 -> row0, t>=128 -> row1 ----
        if (low) {
            float pka = sigm(pb0[cl]) * tanh_fast(pb0[128 + cl]);
            kv0[cl] = greg * kold + (1.f - greg) * pka;
        } else {
            float pka = sigm(pb1[cl]) * tanh_fast(pb1[128 + cl]);
            kv1[cl] = greg * kold + (1.f - greg) * pka;
        }
        __syncthreads();   // B4

        // ---- S5: logits partials; t<80 row0, t in [128,208) row1 ----
        if (cl < 80) {
            int o = cl >> 3, s0i = (cl & 7) * 16;
            const float* wf = sm + OFF_WF + o*128 + s0i;
            const float* kk = (low ? kv0 : kv1) + s0i;
            float acc = 0.f;
            #pragma unroll
            for (int i = 0; i < 16; i += 4) {
                float4 k4 = *reinterpret_cast<const float4*>(kk + i);
                float4 wv = *reinterpret_cast<const float4*>(wf + i);
                acc += k4.x*wv.x + k4.y*wv.y + k4.z*wv.z + k4.w*wv.w;
            }
            (low ? lp0 : lp1)[cl] = acc;
        }
        __syncthreads();   // B5

        if (cl < 10) {
            const float* lp = low ? lp0 : lp1;
            float acc = bfreg;
            #pragma unroll
            for (int u = 0; u < 8; u++) acc += lp[cl*8 + u];
            (low ? outp0 : outp1)[stp*10 + cl] = sigm(acc);
        }
        __syncthreads();   // B6
    }
}

// ---------------------------------------------------------------------------
extern "C" void kernel_launch(void* const* d_in, const int* in_sizes, int n_in,
                              void* d_out, int out_size)
{
    const int* qi = (const int*)d_in[0];
    const int* ci = (const int*)d_in[1];
    const int* si = (const int*)d_in[2];
    const int* di = (const int*)d_in[3];
    const int* ai = (const int*)d_in[4];
    const float* knowledge = (const float*)d_in[9];
    const float* q_tab  = (const float*)d_in[10];
    const float* c_tab  = (const float*)d_in[11];
    const float* sd_tab = (const float*)d_in[12];
    const float* qd_tab = (const float*)d_in[13];
    const float* a_tab  = (const float*)d_in[14];
    const float* W1 = (const float*)d_in[15]; const float* b1 = (const float*)d_in[16];
    const float* W2 = (const float*)d_in[17]; const float* b2 = (const float*)d_in[18];
    const float* W3 = (const float*)d_in[19]; const float* b3 = (const float*)d_in[20];
    const float* W4 = (const float*)d_in[21]; const float* b4 = (const float*)d_in[22];
    const float* W5 = (const float*)d_in[23]; const float* b5 = (const float*)d_in[24];
    const float* W6 = (const float*)d_in[25]; const float* b6 = (const float*)d_in[26];
    const float* Wf = (const float*)d_in[27]; const float* bf = (const float*)d_in[28];
    float* out = (float*)d_out;

    float *pC23, *pW45a, *pb45, *pb23, *pcst, *pG, *pTQ, *pTC, *pTS1, *pTD1, *pTA45, *pTA6, *pTS6, *pTD6;
    cudaGetSymbolAddress((void**)&pC23,  g_C23);
    cudaGetSymbolAddress((void**)&pW45a, g_W45a);
    cudaGetSymbolAddress((void**)&pb45,  g_b45);
    cudaGetSymbolAddress((void**)&pb23,  g_b23);
    cudaGetSymbolAddress((void**)&pcst,  g_cst23);
    cudaGetSymbolAddress((void**)&pG,    g_G);
    cudaGetSymbolAddress((void**)&pTQ,   g_TQ);
    cudaGetSymbolAddress((void**)&pTC,   g_TC);
    cudaGetSymbolAddress((void**)&pTS1,  g_TS1);
    cudaGetSymbolAddress((void**)&pTD1,  g_TD1);
    cudaGetSymbolAddress((void**)&pTA45, g_TA45);
    cudaGetSymbolAddress((void**)&pTA6,  g_TA6);
    cudaGetSymbolAddress((void**)&pTS6,  g_TS6);
    cudaGetSymbolAddress((void**)&pTD6,  g_TD6);

    // launch 0: prep
    prep_concat<<<128, 256>>>(W2, W3, W4, W5, b2, b3, b4, b5);

    // launch 1: batch A — G, cst23, TA45, TA6, TS6, TD6
    {
        GBatch bt; bt.n = 6;
        bt.g[0] = { W1,     pC23,         nullptr, pG,    512, 256 };
        bt.g[1] = { b1,     pC23,         pb23,    pcst,  1,   256 };
        bt.g[2] = { a_tab,  pW45a,        pb45,    pTA45, NA1, 256 };
        bt.g[3] = { a_tab,  W6 + 128*128, b6,      pTA6,  NA1, 128 };
        bt.g[4] = { sd_tab, W6 + 256*128, nullptr, pTS6,  ND1, 128 };
        bt.g[5] = { qd_tab, W6 + 384*128, nullptr, pTD6,  ND1, 128 };
        int s = 0; bt.start[0] = 0;
        for (int i = 0; i < 6; i++) { s += (bt.g[i].M + 63) / 64; bt.start[i+1] = s; }
        gemm_batched<<<s, 256>>>(bt);
    }
    // launch 2: batch B — TQ, TC, TS1, TD1
    {
        GBatch bt; bt.n = 4;
        bt.g[0] = { q_tab,  pG,           pcst,    pTQ,  NQ1, 256 };
        bt.g[1] = { c_tab,  pG + 128*256, nullptr, pTC,  NC1, 256 };
        bt.g[2] = { sd_tab, pG + 256*256, nullptr, pTS1, ND1, 256 };
        bt.g[3] = { qd_tab, pG + 384*256, nullptr, pTD1, ND1, 256 };
        int s = 0; bt.start[0] = 0;
        for (int i = 0; i < 4; i++) { s += (bt.g[i].M + 63) / 64; bt.start[i+1] = s; }
        gemm_batched<<<s, 256>>>(bt);
    }

    // launch 3: scan — 64 CTAs, 2 batch rows each (profiled launch)
    cudaFuncSetAttribute(scan_kernel, cudaFuncAttributeMaxDynamicSharedMemorySize, SCAN_SMEM_BYTES);
    scan_kernel<<<64, 256, SCAN_SMEM_BYTES>>>(qi, ci, si, di, ai, knowledge,
                                              W2, W3, W4, W5, W6, Wf, bf, out);
}

// round 17
// speedup vs baseline: 1.6064x; 1.6064x over previous
#include <cuda_runtime.h>

#define NQ1 10001
#define NC1 301
#define ND1 200
#define NA1 20002

// ---- device scratch (static globals: no runtime allocation) ----
__device__ float g_C23 [128*256];   // [W2|W3] row-major (GEMM B operand)
__device__ float g_W45a[128*256];   // [W4[128:],W5[128:]]
__device__ float g_b45 [256];
__device__ float g_b23 [256];       // [b2|b3]
__device__ float g_cst23[256];      // b1@C23 + [b2|b3]
__device__ float g_G   [512*256];   // W1 @ C23
__device__ float g_TQ  [NQ1*256];
__device__ float g_TC  [NC1*256];
__device__ float g_TS1 [ND1*256];
__device__ float g_TD1 [ND1*256];
__device__ float g_TA45[NA1*256];
__device__ float g_TA6 [NA1*128];
__device__ float g_TS6 [ND1*128];
__device__ float g_TD6 [ND1*128];

__device__ __forceinline__ float tanh_fast(float x) {
    float y; asm("tanh.approx.f32 %0, %1;" : "=f"(y) : "f"(x)); return y;
}
// sigmoid via MUFU tanh: 1 MUFU + 2 FMA
__device__ __forceinline__ float sigm(float x) {
    return fmaf(tanh_fast(0.5f * x), 0.5f, 0.5f);
}

// ---------------------------------------------------------------------------
__global__ void prep_concat(const float* __restrict__ W2, const float* __restrict__ W3,
                            const float* __restrict__ W4, const float* __restrict__ W5,
                            const float* __restrict__ b2, const float* __restrict__ b3,
                            const float* __restrict__ b4, const float* __restrict__ b5)
{
    int e = blockIdx.x * 256 + threadIdx.x;
    if (e < 128*256) {
        int i = e >> 8, j = e & 255;
        g_C23 [e] = (j < 128) ? W2[i*128 + j]       : W3[i*128 + (j-128)];
        g_W45a[e] = (j < 128) ? W4[(128+i)*128 + j] : W5[(128+i)*128 + (j-128)];
    }
    if (e < 256) {
        g_b45[e] = (e < 128) ? b4[e] : b5[e-128];
        g_b23[e] = (e < 128) ? b2[e] : b3[e-128];
    }
}

// ---------------------------------------------------------------------------
// batched table GEMM: C[M,N] = A[M,128]@B[128,N] (+bias)
// 256 thr, 64 rows/block, 8 rows/warp.
// ---------------------------------------------------------------------------
struct GDesc { const float *A, *B, *bias; float *C; int M, N; };
struct GBatch { GDesc g[6]; int start[7]; int n; };

__global__ void gemm_batched(GBatch bt)
{
    __shared__ float As[64*128];
    int gi = 0;
    while (gi < bt.n - 1 && (int)blockIdx.x >= bt.start[gi+1]) gi++;
    const GDesc d = bt.g[gi];
    const int blk = blockIdx.x - bt.start[gi];

    const int tid = threadIdx.x, w = tid >> 5, lane = tid & 31;
    const int row0 = blk * 64;
    for (int e = tid; e < 8192; e += 256) {
        int rr = e >> 7, ii = e & 127, gr = row0 + rr;
        As[e] = (gr < d.M) ? d.A[gr*128 + ii] : 0.f;
    }
    __syncthreads();
    const int r0 = w * 8;
    for (int jo = 0; jo < d.N; jo += 128) {
        const int j = jo + lane * 4;
        float acc[8][4] = {};
        const float* Bp = d.B + j;
        #pragma unroll 2
        for (int i = 0; i < 128; i++) {
            float4 bb = *reinterpret_cast<const float4*>(Bp + i*d.N);
            #pragma unroll
            for (int rr = 0; rr < 8; rr++) {
                float av = As[(r0 + rr)*128 + i];
                acc[rr][0] += av*bb.x; acc[rr][1] += av*bb.y;
                acc[rr][2] += av*bb.z; acc[rr][3] += av*bb.w;
            }
        }
        float4 bv = d.bias ? *reinterpret_cast<const float4*>(d.bias + j)
                           : make_float4(0.f, 0.f, 0.f, 0.f);
        #pragma unroll
        for (int rr = 0; rr < 8; rr++) {
            int row = row0 + r0 + rr;
            if (row < d.M) {
                float4 o;
                o.x = acc[rr][0]+bv.x; o.y = acc[rr][1]+bv.y;
                o.z = acc[rr][2]+bv.z; o.w = acc[rr][3]+bv.w;
                *reinterpret_cast<float4*>(d.C + row*d.N + j) = o;
            }
        }
    }
}

// ---------------------------------------------------------------------------
// scan: one CTA per batch row (128 CTAs, 256 threads) — R7 structure,
// 4 barriers/step: logits for step s-1 pipelined onto idle t>=128 threads.
// ---------------------------------------------------------------------------
#define C23T_STRIDE 132
#define SCAN_SMEM_FLOATS (256*132 + 128*132 + 1280 + 128 + 128 + 256 + 256 + 256 + 80)
#define SCAN_SMEM_BYTES  ((SCAN_SMEM_FLOATS + 5*512) * 4)

__global__ void __launch_bounds__(256, 1)
scan_kernel(const int* __restrict__ qi_, const int* __restrict__ ci_,
            const int* __restrict__ si_, const int* __restrict__ di_,
            const int* __restrict__ ai_,
            const float* __restrict__ knowledge,
            const float* __restrict__ W2, const float* __restrict__ W3,
            const float* __restrict__ W4, const float* __restrict__ W5,
            const float* __restrict__ W6,
            const float* __restrict__ Wf, const float* __restrict__ bf,
            float* __restrict__ out)
{
    extern __shared__ float sm[];
    float* C23t = sm;                    // [col][i], stride 132, col<256
    float* W6t  = C23t + 256*132;        // [col][i], stride 132, col<128
    float* Wfs  = W6t + 128*132;         // 10x128 ([o][i])
    float* kvec = Wfs + 1280;            // 128
    float* sdf  = kvec + 128;            // 128
    float* zb   = sdf + 128;             // 256
    float* g6   = zb + 256;              // 256
    float* pb   = g6 + 256;              // 256
    float* lp   = pb + 256;              // 80
    int*   idxs = (int*)(lp + 80);       // 5*512

    const int b = blockIdx.x, t = threadIdx.x;

    // transposed fills (coalesced global reads)
    for (int e = t; e < 128*256; e += 256) {
        int i = e >> 8, j = e & 255;
        float v = (j < 128) ? W2[i*128 + j] : W3[i*128 + (j-128)];
        C23t[j*C23T_STRIDE + i] = v;
    }
    for (int e = t; e < 128*128; e += 256) {
        int i = e >> 7, cc = e & 127;
        W6t[cc*C23T_STRIDE + i] = W6[i*128 + cc];
    }
    for (int e = t; e < 1280; e += 256) { int o = e >> 7, i = e & 127; Wfs[e] = Wf[i*10 + o]; }
    if (t < 128) kvec[t] = knowledge[t];
    for (int e = t; e < 512; e += 256) {
        int g = b*512 + e;
        idxs[e]        = qi_[g];
        idxs[512 + e]  = ci_[g];
        idxs[1024 + e] = si_[g];
        idxs[1536 + e] = di_[g];
        idxs[2048 + e] = ai_[g];
    }
    // register-resident [W4s|W5s] column t (fully unrolled -> true registers)
    float w45[128];
    {
        const float* Ws = (t < 128) ? W4 : W5;
        const int col = t & 127;
        #pragma unroll
        for (int i = 0; i < 128; i++) w45[i] = Ws[i*128 + col];
    }
    // logits roles: partials by t in [128,208): u = t-128, o = u>>3, seg = (u&7)*16
    //               combine by t in [128,138): o = t-128
    const int u = t - 128;
    const bool lpart = (t >= 128 && t < 208);
    const bool lcomb = (t >= 128 && t < 138);
    const float bfreg = lcomb ? bf[u] : 0.f;
    __syncthreads();

    const bool low = (t < 128);
    const int half0 = (t >> 7) * 64;

    // prefetch step-0 streams
    float xq, xc, xs, xd, a45p, r6a = 0.f, r6s = 0.f, r6d = 0.f;
    {
        int q0 = idxs[0], c0 = idxs[512], s0 = idxs[1024], d0 = idxs[1536], a0 = idxs[2048];
        xq = g_TQ[q0*256 + t];  xc = g_TC[c0*256 + t];
        xs = g_TS1[s0*256 + t]; xd = g_TD1[d0*256 + t];
        a45p = g_TA45[a0*256 + t];
        if (low) { r6a = g_TA6[a0*128 + t]; r6s = g_TS6[s0*128 + t]; r6d = g_TD6[d0*128 + t]; }
    }

    const float* wc = C23t + t*C23T_STRIDE;
    const float* w6 = W6t + (t & 127)*C23T_STRIDE + half0;
    float* outp = out + b * 5120;
    float greg = 0.f, kold = 0.f;

    for (int stp = 0; stp < 512; stp++) {
        const float x23c = (xq + xc) + (xs + xd);
        const float a45c = a45p;
        const float r6c  = (r6a + r6s) + r6d;

        if (stp + 1 < 512) {
            int q1 = idxs[stp+1],      c1 = idxs[512+stp+1], s1 = idxs[1024+stp+1],
                d1 = idxs[1536+stp+1], a1 = idxs[2048+stp+1];
            xq = g_TQ[q1*256 + t];  xc = g_TC[c1*256 + t];
            xs = g_TS1[s1*256 + t]; xd = g_TD1[d1*256 + t];
            a45p = g_TA45[a1*256 + t];
            if (low) { r6a = g_TA6[a1*128 + t]; r6s = g_TS6[s1*128 + t]; r6d = g_TD6[d1*128 + t]; }
        }

        // ---- S1 (all): z col t = x23 - k@C23[:,t]; g6 half-partial via W6t ----
        float A0=0.f,A1=0.f,A2=0.f,A3=0.f;
        #pragma unroll
        for (int i = 0; i < 128; i += 4) {
            float4 k4 = *reinterpret_cast<const float4*>(kvec + i);
            float4 w4 = *reinterpret_cast<const float4*>(wc + i);
            A0 += k4.x * w4.x; A1 += k4.y * w4.y;
            A2 += k4.z * w4.z; A3 += k4.w * w4.w;
        }
        float G0=0.f,G1=0.f,G2=0.f,G3=0.f;
        #pragma unroll
        for (int i = 0; i < 64; i += 4) {
            float4 k4 = *reinterpret_cast<const float4*>(kvec + half0 + i);
            float4 w4 = *reinterpret_cast<const float4*>(w6 + i);
            G0 += k4.x * w4.x; G1 += k4.y * w4.y;
            G2 += k4.z * w4.z; G3 += k4.w * w4.w;
        }
        zb[t] = x23c - ((A0+A1)+(A2+A3));
        g6[t] = (G0+G1)+(G2+G3);
        __syncthreads();   // B1

        // ---- S2: t<128 sdf+gate ; t in [128,208): logits partials for step stp-1 ----
        if (low) {
            sdf[t] = sigm(zb[t]) * tanh_fast(zb[128 + t]);
            greg = sigm(g6[t] + g6[128 + t] + r6c);
            kold = kvec[t];
        } else if (lpart && stp > 0) {
            int o = u >> 3, s0i = (u & 7) * 16;
            const float* wf = Wfs + o*128 + s0i;
            const float* kk = kvec + s0i;     // kvec = state after step stp-1 update
            float acc = 0.f;
            #pragma unroll
            for (int i = 0; i < 16; i += 4) {
                float4 k4 = *reinterpret_cast<const float4*>(kk + i);
                float4 wv = *reinterpret_cast<const float4*>(wf + i);
                acc += k4.x*wv.x + k4.y*wv.y + k4.z*wv.z + k4.w*wv.w;
            }
            lp[u] = acc;
        }
        __syncthreads();   // B2

        // ---- S3 (all): P col t = sdf @ w45 + a45 stream ----
        float P0=0.f,P1=0.f,P2=0.f,P3=0.f;
        #pragma unroll
        for (int i = 0; i < 128; i += 4) {
            float4 s4 = *reinterpret_cast<const float4*>(sdf + i);
            P0 += s4.x * w45[i+0];
            P1 += s4.y * w45[i+1];
            P2 += s4.z * w45[i+2];
            P3 += s4.w * w45[i+3];
        }
        pb[t] = ((P0+P1)+(P2+P3)) + a45c;
        __syncthreads();   // B3

        // ---- S4: t<128 k update ; t in [128,138): combine + write out[stp-1] ----
        if (low) {
            float pka = sigm(pb[t]) * tanh_fast(pb[128 + t]);
            kvec[t] = greg * kold + (1.f - greg) * pka;
        } else if (lcomb && stp > 0) {
            float acc = bfreg;
            #pragma unroll
            for (int v = 0; v < 8; v++) acc += lp[u*8 + v];
            outp[(stp-1)*10 + u] = sigm(acc);
        }
        __syncthreads();   // B4
    }

    // epilogue: logits for final step (511) from final kvec
    if (lpart) {
        int o = u >> 3, s0i = (u & 7) * 16;
        const float* wf = Wfs + o*128 + s0i;
        const float* kk = kvec + s0i;
        float acc = 0.f;
        #pragma unroll
        for (int i = 0; i < 16; i += 4) {
            float4 k4 = *reinterpret_cast<const float4*>(kk + i);
            float4 wv = *reinterpret_cast<const float4*>(wf + i);
            acc += k4.x*wv.x + k4.y*wv.y + k4.z*wv.z + k4.w*wv.w;
        }
        lp[u] = acc;
    }
    __syncthreads();
    if (lcomb) {
        float acc = bfreg;
        #pragma unroll
        for (int v = 0; v < 8; v++) acc += lp[u*8 + v];
        outp[511*10 + u] = sigm(acc);
    }
}

// ---------------------------------------------------------------------------
extern "C" void kernel_launch(void* const* d_in, const int* in_sizes, int n_in,
                              void* d_out, int out_size)
{
    const int* qi = (const int*)d_in[0];
    const int* ci = (const int*)d_in[1];
    const int* si = (const int*)d_in[2];
    const int* di = (const int*)d_in[3];
    const int* ai = (const int*)d_in[4];
    const float* knowledge = (const float*)d_in[9];
    const float* q_tab  = (const float*)d_in[10];
    const float* c_tab  = (const float*)d_in[11];
    const float* sd_tab = (const float*)d_in[12];
    const float* qd_tab = (const float*)d_in[13];
    const float* a_tab  = (const float*)d_in[14];
    const float* W1 = (const float*)d_in[15]; const float* b1 = (const float*)d_in[16];
    const float* W2 = (const float*)d_in[17]; const float* b2 = (const float*)d_in[18];
    const float* W3 = (const float*)d_in[19]; const float* b3 = (const float*)d_in[20];
    const float* W4 = (const float*)d_in[21]; const float* b4 = (const float*)d_in[22];
    const float* W5 = (const float*)d_in[23]; const float* b5 = (const float*)d_in[24];
    const float* W6 = (const float*)d_in[25]; const float* b6 = (const float*)d_in[26];
    const float* Wf = (const float*)d_in[27]; const float* bf = (const float*)d_in[28];
    float* out = (float*)d_out;

    float *pC23, *pW45a, *pb45, *pb23, *pcst, *pG, *pTQ, *pTC, *pTS1, *pTD1, *pTA45, *pTA6, *pTS6, *pTD6;
    cudaGetSymbolAddress((void**)&pC23,  g_C23);
    cudaGetSymbolAddress((void**)&pW45a, g_W45a);
    cudaGetSymbolAddress((void**)&pb45,  g_b45);
    cudaGetSymbolAddress((void**)&pb23,  g_b23);
    cudaGetSymbolAddress((void**)&pcst,  g_cst23);
    cudaGetSymbolAddress((void**)&pG,    g_G);
    cudaGetSymbolAddress((void**)&pTQ,   g_TQ);
    cudaGetSymbolAddress((void**)&pTC,   g_TC);
    cudaGetSymbolAddress((void**)&pTS1,  g_TS1);
    cudaGetSymbolAddress((void**)&pTD1,  g_TD1);
    cudaGetSymbolAddress((void**)&pTA45, g_TA45);
    cudaGetSymbolAddress((void**)&pTA6,  g_TA6);
    cudaGetSymbolAddress((void**)&pTS6,  g_TS6);
    cudaGetSymbolAddress((void**)&pTD6,  g_TD6);

    // launch 0: prep
    prep_concat<<<128, 256>>>(W2, W3, W4, W5, b2, b3, b4, b5);

    // launch 1: batch A — G, cst23, TA45, TA6, TS6, TD6
    {
        GBatch bt; bt.n = 6;
        bt.g[0] = { W1,     pC23,         nullptr, pG,    512, 256 };
        bt.g[1] = { b1,     pC23,         pb23,    pcst,  1,   256 };
        bt.g[2] = { a_tab,  pW45a,        pb45,    pTA45, NA1, 256 };
        bt.g[3] = { a_tab,  W6 + 128*128, b6,      pTA6,  NA1, 128 };
        bt.g[4] = { sd_tab, W6 + 256*128, nullptr, pTS6,  ND1, 128 };
        bt.g[5] = { qd_tab, W6 + 384*128, nullptr, pTD6,  ND1, 128 };
        int s = 0; bt.start[0] = 0;
        for (int i = 0; i < 6; i++) { s += (bt.g[i].M + 63) / 64; bt.start[i+1] = s; }
        gemm_batched<<<s, 256>>>(bt);
    }
    // launch 2: batch B — TQ, TC, TS1, TD1
    {
        GBatch bt; bt.n = 4;
        bt.g[0] = { q_tab,  pG,           pcst,    pTQ,  NQ1, 256 };
        bt.g[1] = { c_tab,  pG + 128*256, nullptr, pTC,  NC1, 256 };
        bt.g[2] = { sd_tab, pG + 256*256, nullptr, pTS1, ND1, 256 };
        bt.g[3] = { qd_tab, pG + 384*256, nullptr, pTD1, ND1, 256 };
        int s = 0; bt.start[0] = 0;
        for (int i = 0; i < 4; i++) { s += (bt.g[i].M + 63) / 64; bt.start[i+1] = s; }
        gemm_batched<<<s, 256>>>(bt);
    }

    // launch 3: scan (profiled launch) — 128 CTAs, one per batch row
    cudaFuncSetAttribute(scan_kernel, cudaFuncAttributeMaxDynamicSharedMemorySize, SCAN_SMEM_BYTES);
    scan_kernel<<<128, 256, SCAN_SMEM_BYTES>>>(qi, ci, si, di, ai, knowledge,
                                               W2, W3, W4, W5, W6, Wf, bf, out);
}